// round 16
// baseline (speedup 1.0000x reference)
#include <cuda_runtime.h>
#include <cuda_bf16.h>

// Problem: DotProductAttention_83476984365340
// softmax over singleton axis == 1.0 -> output = values.sum(axis=1).
// Pure HBM-bound column sum of values [32, 4096, 1024] f32 (512 MiB read).
//
// Config (all axes swept): 256 CTAs (8 chunks x 32 b, 2MiB aligned streams),
// PIPE=9 double-buffered pipeline (~7.0 TB/s, DRAM ~88% = HBM3e wall).
// R16: single-graph-node version. Replaces memset node + 1M atomicAdds with
// a threadfence reduction: chunk CTAs store partials to __device__ scratch,
// last-arriving CTA per batch reduces 8 slots deterministically and writes
// out (full overwrite of the poisoned buffer). Counter reset for graph replay.

#define B_DIM 32
#define T_DIM 4096
#define D_DIM 1024
#define CHUNKS_PER_B 8
#define T_PER_CHUNK (T_DIM / CHUNKS_PER_B)  // 512 rows = 2 MiB per CTA
#define THREADS 256                          // 256 threads * float4 = 1024 = D
#define PIPE 9                               // double-buffer depth
#define FULLG_USED (T_PER_CHUNK / PIPE)      // 56 full groups
#define TAIL (T_PER_CHUNK - FULLG_USED * PIPE)  // 8

// Partial sums [chunk][b][d] and per-batch arrival counters.
__device__ float        g_partial[CHUNKS_PER_B][B_DIM][D_DIM];
__device__ unsigned int g_arrive[B_DIM];     // zero-initialized at load

__global__ __launch_bounds__(THREADS, 2)
void values_colsum_kernel(const float* __restrict__ values, float* __restrict__ out)
{
    const int b  = blockIdx.y;                 // 0..31
    const int c  = blockIdx.x;                 // 0..7
    const int d4 = threadIdx.x;                // float4 lane within row (0..255)

    const float4* __restrict__ p =
        reinterpret_cast<const float4*>(values) +
        (size_t)b * T_DIM * (D_DIM / 4) +
        (size_t)c * T_PER_CHUNK * (D_DIM / 4) +
        d4;

    float4 acc0 = make_float4(0.f, 0.f, 0.f, 0.f);
    float4 acc1 = make_float4(0.f, 0.f, 0.f, 0.f);

    // Prologue: fill buffer A.
    float4 va[PIPE], vb[PIPE];
    #pragma unroll
    for (int k = 0; k < PIPE; ++k)
        va[k] = p[(size_t)k * (D_DIM / 4)];
    p += (size_t)PIPE * (D_DIM / 4);

    // Steady state: 55 iterations of issue-next-then-consume.
    for (int it = 0; it < FULLG_USED - 1; ++it) {
        float4* cur  = (it & 1) ? vb : va;
        float4* next = (it & 1) ? va : vb;

        #pragma unroll
        for (int k = 0; k < PIPE; ++k)
            next[k] = p[(size_t)k * (D_DIM / 4)];
        p += (size_t)PIPE * (D_DIM / 4);

        #pragma unroll
        for (int k = 0; k < PIPE - 1; k += 2) {
            acc0.x += cur[k].x;   acc0.y += cur[k].y;
            acc0.z += cur[k].z;   acc0.w += cur[k].w;
            acc1.x += cur[k+1].x; acc1.y += cur[k+1].y;
            acc1.z += cur[k+1].z; acc1.w += cur[k+1].w;
        }
        acc0.x += cur[PIPE-1].x; acc0.y += cur[PIPE-1].y;
        acc0.z += cur[PIPE-1].z; acc0.w += cur[PIPE-1].w;
    }

    // Epilogue: drain last full group while issuing the 8-row tail, then tail.
    {
        float4* cur = ((FULLG_USED - 1) & 1) ? vb : va;   // 55 odd -> vb
        float4 vt[TAIL];

        #pragma unroll
        for (int k = 0; k < TAIL; ++k)
            vt[k] = p[(size_t)k * (D_DIM / 4)];

        #pragma unroll
        for (int k = 0; k < PIPE - 1; k += 2) {
            acc0.x += cur[k].x;   acc0.y += cur[k].y;
            acc0.z += cur[k].z;   acc0.w += cur[k].w;
            acc1.x += cur[k+1].x; acc1.y += cur[k+1].y;
            acc1.z += cur[k+1].z; acc1.w += cur[k+1].w;
        }
        acc0.x += cur[PIPE-1].x; acc0.y += cur[PIPE-1].y;
        acc0.z += cur[PIPE-1].z; acc0.w += cur[PIPE-1].w;

        #pragma unroll
        for (int k = 0; k < TAIL; k += 2) {
            acc0.x += vt[k].x;   acc0.y += vt[k].y;
            acc0.z += vt[k].z;   acc0.w += vt[k].w;
            acc1.x += vt[k+1].x; acc1.y += vt[k+1].y;
            acc1.z += vt[k+1].z; acc1.w += vt[k+1].w;
        }
    }

    acc0.x += acc1.x; acc0.y += acc1.y; acc0.z += acc1.z; acc0.w += acc1.w;

    // Publish partial sum (plain store, race-free: unique slot per CTA).
    reinterpret_cast<float4*>(g_partial[c][b])[d4] = acc0;

    // Release: make partials visible device-wide, then arrive.
    __threadfence();
    __syncthreads();

    __shared__ int s_last;
    if (threadIdx.x == 0)
        s_last = (atomicAdd(&g_arrive[b], 1u) == CHUNKS_PER_B - 1) ? 1 : 0;
    __syncthreads();

    if (s_last) {
        // Last-arriving CTA for this batch: reduce 8 slots deterministically.
        // __ldcg bypasses L1 -> sees the other CTAs' L2-visible stores.
        float4 sum = make_float4(0.f, 0.f, 0.f, 0.f);
        #pragma unroll
        for (int cc = 0; cc < CHUNKS_PER_B; ++cc) {
            const float4* s4 = reinterpret_cast<const float4*>(g_partial[cc][b]) + d4;
            float x  = __ldcg(&(((const float*)s4)[0]));
            float y  = __ldcg(&(((const float*)s4)[1]));
            float z  = __ldcg(&(((const float*)s4)[2]));
            float w  = __ldcg(&(((const float*)s4)[3]));
            sum.x += x; sum.y += y; sum.z += z; sum.w += w;
        }
        reinterpret_cast<float4*>(out + (size_t)b * D_DIM)[d4] = sum;

        // Reset counter for the next graph replay (all arrivals consumed).
        __syncthreads();
        if (threadIdx.x == 0)
            atomicExch(&g_arrive[b], 0u);
    }
}

extern "C" void kernel_launch(void* const* d_in, const int* in_sizes, int n_in,
                              void* d_out, int out_size)
{
    // Input order per reference setup_inputs(): query, keys, values, W
    const float* values = (const float*)d_in[2];
    float* out = (float*)d_out;

    // Single graph node: kernel fully overwrites out, no memset needed.
    dim3 grid(CHUNKS_PER_B, B_DIM);
    values_colsum_kernel<<<grid, THREADS>>>(values, out);
}

// round 17
// speedup vs baseline: 1.0103x; 1.0103x over previous
#include <cuda_runtime.h>
#include <cuda_bf16.h>

// Problem: DotProductAttention_83476984365340
// softmax over singleton axis == 1.0 -> output = values.sum(axis=1).
// Pure HBM-bound column sum of values [32, 4096, 1024] f32 (512 MiB read).
//
// FINAL — all axes swept and bracketed:
//   grid: 256 CTAs = 8 chunks x 32 batches (1.7/SM, 2MiB aligned stream/CTA)
//     [148: 6.39 | 256: ~7.0 | 296: 6.67 | 512: 6.61 | 1024: 6.38 TB/s]
//   depth (double-buffered software pipeline, issue-next-before-consume):
//     [8: 6.96 | 9: 6.98 | 10: 7.10/6.96 | 11: 6.77 | 12: 6.77 TB/s]
//   caching: default ( .cs regressed )
//   epilogue: memset node + atomicAdd (threadfence reduction cost +2.9us kernel)
// Champion: ncu ~77.7us, ~7.0 TB/s, DRAM ~88% — HBM3e streaming wall;
// compute pipes ~4%; 512 MiB traffic irreducible.

#define B_DIM 32
#define T_DIM 4096
#define D_DIM 1024
#define CHUNKS_PER_B 8
#define T_PER_CHUNK (T_DIM / CHUNKS_PER_B)  // 512 rows = 2 MiB per CTA
#define THREADS 256                          // 256 threads * float4 = 1024 = D
#define PIPE 9                               // double-buffer depth
#define FULLG_USED (T_PER_CHUNK / PIPE)      // 56 full groups
#define TAIL (T_PER_CHUNK - FULLG_USED * PIPE)  // 8

__global__ __launch_bounds__(THREADS, 2)
void values_colsum_kernel(const float* __restrict__ values, float* __restrict__ out)
{
    const int b  = blockIdx.y;                 // 0..31
    const int c  = blockIdx.x;                 // 0..7
    const int d4 = threadIdx.x;                // float4 lane within row (0..255)

    const float4* __restrict__ p =
        reinterpret_cast<const float4*>(values) +
        (size_t)b * T_DIM * (D_DIM / 4) +
        (size_t)c * T_PER_CHUNK * (D_DIM / 4) +
        d4;

    float4 acc0 = make_float4(0.f, 0.f, 0.f, 0.f);
    float4 acc1 = make_float4(0.f, 0.f, 0.f, 0.f);

    // Prologue: fill buffer A.
    float4 va[PIPE], vb[PIPE];
    #pragma unroll
    for (int k = 0; k < PIPE; ++k)
        va[k] = p[(size_t)k * (D_DIM / 4)];
    p += (size_t)PIPE * (D_DIM / 4);

    // Steady state: FULLG_USED-1 = 55 iterations of issue-next-then-consume.
    for (int it = 0; it < FULLG_USED - 1; ++it) {
        float4* cur  = (it & 1) ? vb : va;
        float4* next = (it & 1) ? va : vb;

        #pragma unroll
        for (int k = 0; k < PIPE; ++k)
            next[k] = p[(size_t)k * (D_DIM / 4)];
        p += (size_t)PIPE * (D_DIM / 4);

        #pragma unroll
        for (int k = 0; k < PIPE - 1; k += 2) {
            acc0.x += cur[k].x;   acc0.y += cur[k].y;
            acc0.z += cur[k].z;   acc0.w += cur[k].w;
            acc1.x += cur[k+1].x; acc1.y += cur[k+1].y;
            acc1.z += cur[k+1].z; acc1.w += cur[k+1].w;
        }
        // Odd element (PIPE=9).
        acc0.x += cur[PIPE-1].x; acc0.y += cur[PIPE-1].y;
        acc0.z += cur[PIPE-1].z; acc0.w += cur[PIPE-1].w;
    }

    // Epilogue: drain last full group while issuing the 8-row tail, then tail.
    // (FULLG_USED-1 = 55 odd -> last filled buffer is vb.)
    {
        float4* cur = ((FULLG_USED - 1) & 1) ? vb : va;
        float4 vt[TAIL];

        #pragma unroll
        for (int k = 0; k < TAIL; ++k)
            vt[k] = p[(size_t)k * (D_DIM / 4)];

        #pragma unroll
        for (int k = 0; k < PIPE - 1; k += 2) {
            acc0.x += cur[k].x;   acc0.y += cur[k].y;
            acc0.z += cur[k].z;   acc0.w += cur[k].w;
            acc1.x += cur[k+1].x; acc1.y += cur[k+1].y;
            acc1.z += cur[k+1].z; acc1.w += cur[k+1].w;
        }
        acc0.x += cur[PIPE-1].x; acc0.y += cur[PIPE-1].y;
        acc0.z += cur[PIPE-1].z; acc0.w += cur[PIPE-1].w;

        #pragma unroll
        for (int k = 0; k < TAIL; k += 2) {
            acc0.x += vt[k].x;   acc0.y += vt[k].y;
            acc0.z += vt[k].z;   acc0.w += vt[k].w;
            acc1.x += vt[k+1].x; acc1.y += vt[k+1].y;
            acc1.z += vt[k+1].z; acc1.w += vt[k+1].w;
        }
    }

    acc0.x += acc1.x; acc0.y += acc1.y; acc0.z += acc1.z; acc0.w += acc1.w;

    float* o = out + (size_t)b * D_DIM + d4 * 4;
    atomicAdd(o + 0, acc0.x);
    atomicAdd(o + 1, acc0.y);
    atomicAdd(o + 2, acc0.z);
    atomicAdd(o + 3, acc0.w);
}

extern "C" void kernel_launch(void* const* d_in, const int* in_sizes, int n_in,
                              void* d_out, int out_size)
{
    // Input order per reference setup_inputs(): query, keys, values, W
    const float* values = (const float*)d_in[2];
    float* out = (float*)d_out;

    cudaMemsetAsync(out, 0, (size_t)out_size * sizeof(float));

    dim3 grid(CHUNKS_PER_B, B_DIM);
    values_colsum_kernel<<<grid, THREADS>>>(values, out);
}